// round 8
// baseline (speedup 1.0000x reference)
#include <cuda_runtime.h>
#include <cstdint>

// CRF forward (linear-chain log-partition), B=64, T=2048, K=256.
// 1 cluster (2 CTAs) per batch row, 256 threads/CTA. Column-split: CTA r holds
// E[j, i] for ALL 256 j but only its own 128 i-columns, register-resident
// (64 f32x2 per thread; thread tid owns row j = tid). FMA uses only LOCAL p.
// Each thread sends its pre-reduced half dot-product to the peer (st.async,
// 1 KB/step); duplicated tails on both CTAs rebuild identical full scores, so
// p is published locally (STS + warp mbarrier.arrive). No __syncthreads or
// cluster barrier in the main loop. Rescale shift = s[JSTAR], lagged 2 steps.

#define KSZ 256
#define TSZ 2048
#define NEGV -10000.0f
#define SOSI 2
#define JSTAR 16

__device__ __forceinline__ float ex2f(float x) {
    float r; asm("ex2.approx.ftz.f32 %0, %1;" : "=f"(r) : "f"(x)); return r;
}
__device__ __forceinline__ float lg2f_(float x) {
    float r; asm("lg2.approx.ftz.f32 %0, %1;" : "=f"(r) : "f"(x)); return r;
}
__device__ __forceinline__ void unpack2(unsigned long long v, float& lo, float& hi) {
    asm("mov.b64 {%0, %1}, %2;" : "=f"(lo), "=f"(hi) : "l"(v));
}
__device__ __forceinline__ unsigned long long pack2(float lo, float hi) {
    unsigned long long r; asm("mov.b64 %0, {%1, %2};" : "=l"(r) : "f"(lo), "f"(hi)); return r;
}
__device__ __forceinline__ void fma2(unsigned long long& d, unsigned long long a, unsigned long long b) {
    asm("fma.rn.f32x2 %0, %1, %2, %0;" : "+l"(d) : "l"(a), "l"(b));
}
__device__ __forceinline__ uint32_t smem_u32(const void* p) {
    uint32_t a;
    asm("{ .reg .u64 t; cvta.to.shared.u64 t, %1; cvt.u32.u64 %0, t; }" : "=r"(a) : "l"(p));
    return a;
}
__device__ __forceinline__ uint32_t mapa_u32(uint32_t a, uint32_t rk) {
    uint32_t r; asm("mapa.shared::cluster.u32 %0, %1, %2;" : "=r"(r) : "r"(a), "r"(rk)); return r;
}
// Remote store delivering tx-bytes to the destination CTA's mbarrier.
__device__ __forceinline__ void st_async_b32(uint32_t dst_addr, float v, uint32_t dst_bar) {
    asm volatile("st.async.shared::cluster.mbarrier::complete_tx::bytes.b32 [%0], %1, [%2];"
                 :: "r"(dst_addr), "r"(__float_as_uint(v)), "r"(dst_bar) : "memory");
}
__device__ __forceinline__ void mbar_init(uint32_t bar, uint32_t cnt) {
    asm volatile("mbarrier.init.shared.b64 [%0], %1;" :: "r"(bar), "r"(cnt) : "memory");
}
__device__ __forceinline__ void mbar_expect_tx(uint32_t bar, uint32_t bytes) {
    asm volatile("mbarrier.arrive.expect_tx.shared.b64 _, [%0], %1;" :: "r"(bar), "r"(bytes) : "memory");
}
__device__ __forceinline__ void mbar_arrive(uint32_t bar) {
    asm volatile("mbarrier.arrive.shared.b64 _, [%0];" :: "r"(bar) : "memory");
}
__device__ __forceinline__ void mbar_wait_parity(uint32_t bar, uint32_t par) {
    asm volatile(
        "{\n\t.reg .pred P;\n\t"
        "WL_%=:\n\t"
        "mbarrier.try_wait.parity.acquire.cta.shared::cta.b64 P, [%0], %1, 0x989680;\n\t"
        "@P bra.uni WD_%=;\n\t"
        "bra.uni WL_%=;\n\t"
        "WD_%=:\n\t}"
        :: "r"(bar), "r"(par) : "memory");
}
__device__ __forceinline__ void cluster_barrier() {
    asm volatile("barrier.cluster.arrive.aligned;" ::: "memory");
    asm volatile("barrier.cluster.wait.aligned;"   ::: "memory");
}

__global__ void __cluster_dims__(2, 1, 1) __launch_bounds__(256, 1)
crf_fwd_kernel(const float* __restrict__ y,
               const float* __restrict__ mask,
               const float* __restrict__ trans,
               float* __restrict__ out)
{
    constexpr float INV_LN2 = 1.4426950408889634f;
    constexpr float LN2F    = 0.6931471805599453f;

    __shared__ float mask_s[TSZ];                        // 8 KB
    __shared__ __align__(16) float p_s[2][128];          // local-half p, double-buffered
    __shared__ float rpart_s[2][KSZ];                    // peer half dot-products
    __shared__ float mu_s[2];                            // lagged rescale shift
    __shared__ float sfin_s[KSZ];                        // final scores
    __shared__ __align__(8) unsigned long long mbarP[2]; // rx remote partials (tx-based)
    __shared__ __align__(8) unsigned long long mbarPP[2];// local p published (count-based)

    const int tid = threadIdx.x;          // == j, the row this thread owns
    uint32_t rank; asm("mov.u32 %0, %%cluster_ctarank;" : "=r"(rank));
    const uint32_t peer = rank ^ 1u;
    const int b = blockIdx.x >> 1;

    // ---------------- setup ----------------
    if (tid == 0) {
        mbar_init(smem_u32(&mbarP[0]), 1);
        mbar_init(smem_u32(&mbarP[1]), 1);
        const uint32_t cnt = (rank == 0) ? 4u : 5u;   // 4 warp-arrives (+JSTAR on rank1)
        mbar_init(smem_u32(&mbarPP[0]), cnt);
        mbar_init(smem_u32(&mbarPP[1]), cnt);
        mu_s[0] = 0.0f; mu_s[1] = 0.0f;
    }
    for (int i = tid; i < TSZ; i += 256) mask_s[i] = mask[(size_t)b * TSZ + i];
    if ((tid >> 7) == (int)rank)                        // own-range threads init p0
        p_s[0][tid & 127] = (tid == SOSI) ? 1.0f : 0.0f; // p0 = exp(s0 - 0)

    // Full-row max (must be identical on both CTAs: over all 256 columns).
    float Mj;
    {
        const float* row = trans + (size_t)tid * KSZ;
        float mx = row[0];
        #pragma unroll 8
        for (int i = 1; i < KSZ; i++) mx = fmaxf(mx, row[i]);
        Mj = mx;
    }
    // Register-resident E: this CTA's 128 columns of row tid, as 64 f32x2.
    unsigned long long E2[64];
    {
        const float* row = trans + (size_t)tid * KSZ + (int)rank * 128;
        #pragma unroll 16
        for (int k = 0; k < 64; k++) {
            float e0 = ex2f((row[2 * k]     - Mj) * INV_LN2);
            float e1 = ex2f((row[2 * k + 1] - Mj) * INV_LN2);
            E2[k] = pack2(e0, e1);
        }
    }

    // Peer addresses for this thread's partial sends.
    const uint32_t pa_r0 = mapa_u32(smem_u32(&rpart_s[0][tid]), peer);
    const uint32_t pa_r1 = mapa_u32(smem_u32(&rpart_s[1][tid]), peer);
    const uint32_t pa_b0 = mapa_u32(smem_u32(&mbarP[0]), peer);
    const uint32_t pa_b1 = mapa_u32(smem_u32(&mbarP[1]), peer);

    float prev_sf  = (tid == SOSI) ? 0.0f : NEGV;
    float mu_carry = 0.0f;                               // shift p_t was built with
    float y_next   = __ldg(&y[(size_t)b * TSZ * KSZ + tid]);

    const bool own = ((tid >> 7) == (int)rank);
    const bool arr = (own && (tid & 31) == 0) || (rank == 1 && tid == JSTAR);

    __syncthreads();
    cluster_barrier();   // barrier/smem init visible before any peer st.async

    // ---------------- sequential scan over T ----------------
    for (int t = 0; t < TSZ; t++) {
        const int pb = t & 1, nb = pb ^ 1;

        if (tid == 0) mbar_expect_tx(smem_u32(&mbarP[pb]), 1024);  // 256 x 4B

        const float y_cur = y_next;
        if (t + 1 < TSZ)
            y_next = __ldg(&y[((size_t)b * TSZ + (t + 1)) * KSZ + tid]);

        if (t > 0)   // p for this step published at tail t-1
            mbar_wait_parity(smem_u32(&mbarPP[pb]), ((unsigned)(t - 1) >> 1) & 1u);
        const float mu_new = mu_s[pb];   // shift the p being consumed... used for NEXT p

        // Half dot-product over this CTA's 128 i-columns: 64 packed FMAs.
        unsigned long long a0 = 0ull, a1 = 0ull, a2 = 0ull, a3 = 0ull;
        const ulonglong2* pp = reinterpret_cast<const ulonglong2*>(p_s[pb]);
        #pragma unroll
        for (int q = 0; q < 16; q++) {
            ulonglong2 v1 = pp[2 * q];       // broadcast LDS.128
            ulonglong2 v2 = pp[2 * q + 1];
            fma2(a0, E2[4 * q],     v1.x);
            fma2(a1, E2[4 * q + 1], v1.y);
            fma2(a2, E2[4 * q + 2], v2.x);
            fma2(a3, E2[4 * q + 3], v2.y);
        }
        float x0, x1, x2, x3, x4, x5, x6, x7;
        unpack2(a0, x0, x1); unpack2(a1, x2, x3);
        unpack2(a2, x4, x5); unpack2(a3, x6, x7);
        const float P = ((x0 + x2) + (x1 + x3)) + ((x4 + x6) + (x5 + x7));

        // Ship my half to the peer (it rebuilds the same v for row tid).
        st_async_b32(pb ? pa_r1 : pa_r0, P, pb ? pa_b1 : pa_b0);

        // Wait for the peer's halves, then finish the recurrence (duplicated tail).
        mbar_wait_parity(smem_u32(&mbarP[pb]), ((unsigned)t >> 1) & 1u);
        const float v  = P + rpart_s[pb][tid];           // commutative: identical on both CTAs
        const float sn = y_cur + lg2f_(v) * LN2F + Mj + mu_carry;
        const float sf = (mask_s[t] > 0.5f) ? sn : prev_sf;
        prev_sf = sf;
        const float pv = ex2f((sf - mu_new) * INV_LN2);
        mu_carry = mu_new;                               // next step's sn uses this shift

        if (own) p_s[nb][tid & 127] = pv;                // publish local half of p
        if (tid == JSTAR) mu_s[nb] = sf;                 // broadcast next shift (lag 2)
        __syncwarp();
        if (arr) mbar_arrive(smem_u32(&mbarPP[nb]));
    }

    // ---------------- final logsumexp over K (scores duplicated; rank 0 writes) ----
    sfin_s[tid] = prev_sf;
    __syncthreads();
    if (rank == 0 && tid < 32) {
        float mx = -3.4e38f;
        #pragma unroll
        for (int k = 0; k < 8; k++) mx = fmaxf(mx, sfin_s[tid + 32 * k]);
        #pragma unroll
        for (int o = 16; o; o >>= 1) mx = fmaxf(mx, __shfl_xor_sync(0xffffffffu, mx, o));
        float sum = 0.0f;
        #pragma unroll
        for (int k = 0; k < 8; k++) sum += ex2f((sfin_s[tid + 32 * k] - mx) * INV_LN2);
        #pragma unroll
        for (int o = 16; o; o >>= 1) sum += __shfl_xor_sync(0xffffffffu, sum, o);
        if (tid == 0) out[b] = mx + lg2f_(sum) * LN2F;
    }
    cluster_barrier();   // no CTA exits while peer st.asyncs could be in flight
}

extern "C" void kernel_launch(void* const* d_in, const int* in_sizes, int n_in,
                              void* d_out, int out_size)
{
    const float* y     = (const float*)d_in[0];   // (B, T, K) f32
    const float* mask  = (const float*)d_in[1];   // (B, T)    f32
    const float* trans = (const float*)d_in[2];   // (K, K)    f32
    float* out = (float*)d_out;                   // (B,)      f32

    const int B = in_sizes[1] / TSZ;              // 64
    crf_fwd_kernel<<<2 * B, 256>>>(y, mask, trans, out);
}